// round 9
// baseline (speedup 1.0000x reference)
#include <cuda_runtime.h>
#include <cstdint>

// ---------------------------------------------------------------------------
// Problem constants
// ---------------------------------------------------------------------------
#define T_  2048
#define B_  256
#define I_  64
#define H_  128
#define G4_ 512   // 4*H
#define NH_ 512
#define O_  64

// Device-global scratch (allocation-free rule)
__device__ float g_xg[(size_t)T_ * B_ * G4_];   // [T,B,4H]
__device__ float g_hs[(size_t)T_ * B_ * H_];    // [T,B,H]
__device__ float g_Wxh[I_ * G4_];               // [k=64][g=512] tf32 hi (transposed W_ih)
__device__ float g_Wxl[I_ * G4_];
__device__ float g_W1h[H_ * NH_];               // [k=128][nh=512] tf32 hi (transposed W1)
__device__ float g_W1l[H_ * NH_];
__device__ float g_W2h[NH_ * O_];               // [nh=512][o=64]  tf32 hi (transposed W2)
__device__ float g_W2l[NH_ * O_];

// Output layout: out[T,B,O] | hT[1,B,H] | cT[1,B,H]
#define OUT_ELEMS ((size_t)T_ * B_ * O_)
#define HT_OFF    (OUT_ELEMS)
#define CT_OFF    (OUT_ELEMS + (size_t)B_ * H_)

__device__ __forceinline__ float sigf(float x)      { return 1.f / (1.f + __expf(-x)); }
__device__ __forceinline__ float tanhfast(float x)  { return 2.f / (1.f + __expf(-2.f * x)) - 1.f; }

// ---------------------------------------------------------------------------
// tf32 helpers (mma.sync works on base sm_103; tcgen05 does not — harness
// emits compute_103 PTX without the 'a' suffix)
// ---------------------------------------------------------------------------
__device__ __forceinline__ void tf32_split(float a, uint32_t& hi, uint32_t& lo) {
    uint32_t h;
    asm("cvt.rna.tf32.f32 %0, %1;" : "=r"(h) : "f"(a));
    float r = a - __uint_as_float(h);
    uint32_t l;
    asm("cvt.rna.tf32.f32 %0, %1;" : "=r"(l) : "f"(r));
    hi = h; lo = l;
}

__device__ __forceinline__ void mma8(float* d, const uint32_t* a, const uint32_t* b) {
    asm volatile("mma.sync.aligned.m16n8k8.row.col.f32.tf32.tf32.f32 "
                 "{%0,%1,%2,%3}, {%4,%5,%6,%7}, {%8,%9}, {%0,%1,%2,%3};"
                 : "+f"(d[0]), "+f"(d[1]), "+f"(d[2]), "+f"(d[3])
                 : "r"(a[0]), "r"(a[1]), "r"(a[2]), "r"(a[3]), "r"(b[0]), "r"(b[1]));
}

// ---------------------------------------------------------------------------
// Kernel P: pre-split weights into tf32 hi/lo planes (transposed for col-major B)
// ---------------------------------------------------------------------------
__global__ void prep_kernel(const float* __restrict__ Wih,
                            const float* __restrict__ W1,
                            const float* __restrict__ W2) {
    int i0 = blockIdx.x * blockDim.x + threadIdx.x;
    int st = gridDim.x * blockDim.x;
    for (int i = i0; i < G4_ * I_; i += st) {        // W_ih [g][k] -> [k][g]
        int g = i >> 6, k = i & 63;
        uint32_t h, l;
        tf32_split(Wih[i], h, l);
        g_Wxh[k * G4_ + g] = __uint_as_float(h);
        g_Wxl[k * G4_ + g] = __uint_as_float(l);
    }
    for (int i = i0; i < NH_ * H_; i += st) {        // W1 [nh][k] -> [k][nh]
        int nh = i >> 7, k = i & 127;
        uint32_t h, l;
        tf32_split(W1[i], h, l);
        g_W1h[k * NH_ + nh] = __uint_as_float(h);
        g_W1l[k * NH_ + nh] = __uint_as_float(l);
    }
    for (int i = i0; i < O_ * NH_; i += st) {        // W2 [o][nh] -> [nh][o]
        int o = i >> 9, nh = i & 511;
        uint32_t h, l;
        tf32_split(W2[i], h, l);
        g_W2h[nh * O_ + o] = __uint_as_float(h);
        g_W2l[nh * O_ + o] = __uint_as_float(l);
    }
}

// ---------------------------------------------------------------------------
// Kernel A (mma): xg[row,g] = x @ W_ih^T + bias.  128 rows/CTA, 8 gate-chunks
// of 64.  A (x) pre-split into hi/lo tf32 planes at staging; 3xTF32 mma.
// SMEM 108.5KB -> 2 CTAs/SM.  Strides: A 68 (=4 mod 32), B 72 (=8 mod 32).
// ---------------------------------------------------------------------------
#define XAh_ 0
#define XAl_ (XAh_ + 128 * 68)    // 8704
#define XBh_ (XAl_ + 128 * 68)    // 17408
#define XBl_ (XBh_ +  64 * 72)    // 22016
#define XBI_ (XBl_ +  64 * 72)    // 26624
#define XG_SMEM_BYTES ((XBI_ + 512) * 4)   // 108544

__global__ void __launch_bounds__(256, 2) xg_mma_kernel(const float* __restrict__ x,
                                                        const float* __restrict__ bih,
                                                        const float* __restrict__ bhh) {
    extern __shared__ float sm[];
    const int tid = threadIdx.x;
    const int lane = tid & 31;
    const int w = tid >> 5;
    const int mg = w & 3;          // 4 row groups of 32
    const int nh2 = w >> 2;        // 2 col halves of 32
    const size_t rowBase = (size_t)blockIdx.x * 128;

    const int rA = mg * 32 + (lane >> 2);
    const int kA = lane & 3;
    const int cB = lane >> 2;
    const int kB = lane & 3;

    // stage x tile [128][64], split hi/lo at staging
    for (int i = tid; i < 2048; i += 256) {
        int r = i >> 4, c4 = i & 15;
        float4 v = reinterpret_cast<const float4*>(x)[(rowBase + r) * 16 + c4];
        uint32_t h, l;
        float* dh = &sm[XAh_ + r * 68 + c4 * 4];
        float* dl = &sm[XAl_ + r * 68 + c4 * 4];
        tf32_split(v.x, h, l); dh[0] = __uint_as_float(h); dl[0] = __uint_as_float(l);
        tf32_split(v.y, h, l); dh[1] = __uint_as_float(h); dl[1] = __uint_as_float(l);
        tf32_split(v.z, h, l); dh[2] = __uint_as_float(h); dl[2] = __uint_as_float(l);
        tf32_split(v.w, h, l); dh[3] = __uint_as_float(h); dl[3] = __uint_as_float(l);
    }
    for (int i = tid; i < G4_; i += 256) sm[XBI_ + i] = bih[i] + bhh[i];

    for (int ch = 0; ch < 8; ch++) {
        __syncthreads();   // protect B buffers (and A staging on ch=0)
        for (int i = tid; i < 1024; i += 256) {     // B chunk [64 k][64 g] hi/lo
            int k = i >> 4, n4 = i & 15;
            *reinterpret_cast<float4*>(&sm[XBh_ + k * 72 + n4 * 4]) =
                reinterpret_cast<const float4*>(g_Wxh)[k * 128 + ch * 16 + n4];
            *reinterpret_cast<float4*>(&sm[XBl_ + k * 72 + n4 * 4]) =
                reinterpret_cast<const float4*>(g_Wxl)[k * 128 + ch * 16 + n4];
        }
        __syncthreads();

        float acc[2][4][4];
#pragma unroll
        for (int mf = 0; mf < 2; mf++)
#pragma unroll
            for (int nt = 0; nt < 4; nt++)
#pragma unroll
                for (int q = 0; q < 4; q++) acc[mf][nt][q] = 0.f;

#pragma unroll
        for (int ks = 0; ks < 8; ks++) {
            uint32_t Ah[2][4], Al[2][4];
#pragma unroll
            for (int mf = 0; mf < 2; mf++) {
                int r = rA + mf * 16;
                int k = ks * 8 + kA;
                Ah[mf][0] = __float_as_uint(sm[XAh_ + r * 68 + k]);
                Ah[mf][1] = __float_as_uint(sm[XAh_ + (r + 8) * 68 + k]);
                Ah[mf][2] = __float_as_uint(sm[XAh_ + r * 68 + k + 4]);
                Ah[mf][3] = __float_as_uint(sm[XAh_ + (r + 8) * 68 + k + 4]);
                Al[mf][0] = __float_as_uint(sm[XAl_ + r * 68 + k]);
                Al[mf][1] = __float_as_uint(sm[XAl_ + (r + 8) * 68 + k]);
                Al[mf][2] = __float_as_uint(sm[XAl_ + r * 68 + k + 4]);
                Al[mf][3] = __float_as_uint(sm[XAl_ + (r + 8) * 68 + k + 4]);
            }
#pragma unroll
            for (int nt = 0; nt < 4; nt++) {
                int n = nh2 * 32 + nt * 8 + cB;
                int k = ks * 8 + kB;
                uint32_t Bh[2], Bl[2];
                Bh[0] = __float_as_uint(sm[XBh_ + k * 72 + n]);
                Bh[1] = __float_as_uint(sm[XBh_ + (k + 4) * 72 + n]);
                Bl[0] = __float_as_uint(sm[XBl_ + k * 72 + n]);
                Bl[1] = __float_as_uint(sm[XBl_ + (k + 4) * 72 + n]);
#pragma unroll
                for (int mf = 0; mf < 2; mf++) {
                    mma8(acc[mf][nt], Ah[mf], Bh);
                    mma8(acc[mf][nt], Al[mf], Bh);
                    mma8(acc[mf][nt], Ah[mf], Bl);
                }
            }
        }

        // write chunk to g_xg (+bias)
#pragma unroll
        for (int mf = 0; mf < 2; mf++) {
            size_t r0 = rowBase + rA + mf * 16;
#pragma unroll
            for (int nt = 0; nt < 4; nt++) {
                int col = ch * 64 + nh2 * 32 + nt * 8 + (lane & 3) * 2;
                float bb0 = sm[XBI_ + col];
                float bb1 = sm[XBI_ + col + 1];
                float2 v0, v1;
                v0.x = acc[mf][nt][0] + bb0;
                v0.y = acc[mf][nt][1] + bb1;
                v1.x = acc[mf][nt][2] + bb0;
                v1.y = acc[mf][nt][3] + bb1;
                *reinterpret_cast<float2*>(&g_xg[r0 * G4_ + col]) = v0;
                *reinterpret_cast<float2*>(&g_xg[(r0 + 8) * G4_ + col]) = v1;
            }
        }
    }
}

// ---------------------------------------------------------------------------
// Kernel B: persistent LSTM scan.  KS=80 k in SMEM (160KB), KR=48 k in regs
// (96 weight regs/thread) -> SMEM crossbar no longer binding.
// ---------------------------------------------------------------------------
#define KS_ 80
#define KR_ 48
#define LSTM_SMEM_BYTES ((G4_ * KS_ + 2 * H_ + 8 * H_) * 4)   // 168960

__global__ void __launch_bounds__(256, 1) lstm_kernel(const float* __restrict__ Whh,
                                                      float* __restrict__ outp) {
    extern __shared__ float smem[];
    float* sW = smem;                 // [512][80]
    float* sH = sW + G4_ * KS_;       // [2][128]
    float* sG = sH + 2 * H_;          // [4 types][2 rows][128 units]

    const int tid = threadIdx.x;
    const int row0 = blockIdx.x * 2;
    const int g0 = tid, g1 = tid + 256;

    const float4* W4 = reinterpret_cast<const float4*>(Whh);
    float4* sW4 = reinterpret_cast<float4*>(sW);
    for (int idx = tid; idx < G4_ * 20; idx += 256) {
        int g = idx / 20, k4 = idx % 20;
        sW4[g * 20 + k4] = W4[g * 32 + k4];
    }
    float rw0[KR_], rw1[KR_];
#pragma unroll
    for (int j = 0; j < KR_; j++) {
        rw0[j] = Whh[g0 * H_ + KS_ + j];
        rw1[j] = Whh[g1 * H_ + KS_ + j];
    }
    sH[tid] = 0.f;
    float c = 0.f;
    float h_last = 0.f;
    __syncthreads();

    const float4* w0p = sW4 + g0 * 20;
    const float4* w1p = sW4 + g1 * 20;
    const float4* h0p = reinterpret_cast<const float4*>(sH);
    const float4* h1p = reinterpret_cast<const float4*>(sH + H_);

    size_t pb0 = (size_t)row0 * G4_;
    float xn00 = g_xg[pb0 + g0], xn01 = g_xg[pb0 + G4_ + g0];
    float xn10 = g_xg[pb0 + g1], xn11 = g_xg[pb0 + G4_ + g1];

    const int b_upd = tid >> 7, u_upd = tid & 127;
    const bool isTanh = (g1 < 384);

    for (int t = 0; t < T_; t++) {
        float a00 = xn00, a01 = xn01, a10 = xn10, a11 = xn11;
        if (t + 1 < T_) {
            size_t nb = ((size_t)(t + 1) * B_ + row0) * G4_;
            xn00 = g_xg[nb + g0]; xn01 = g_xg[nb + G4_ + g0];
            xn10 = g_xg[nb + g1]; xn11 = g_xg[nb + G4_ + g1];
        }
#pragma unroll 10
        for (int k4 = 0; k4 < 20; k4++) {
            float4 w0 = w0p[k4], w1 = w1p[k4];
            float4 h0 = h0p[k4], h1 = h1p[k4];
            a00 += w0.x * h0.x + w0.y * h0.y + w0.z * h0.z + w0.w * h0.w;
            a01 += w0.x * h1.x + w0.y * h1.y + w0.z * h1.z + w0.w * h1.w;
            a10 += w1.x * h0.x + w1.y * h0.y + w1.z * h0.z + w1.w * h0.w;
            a11 += w1.x * h1.x + w1.y * h1.y + w1.z * h1.z + w1.w * h1.w;
        }
#pragma unroll
        for (int j4 = 0; j4 < 12; j4++) {   // register tail k = 80..127
            float4 h0 = h0p[20 + j4], h1 = h1p[20 + j4];
            a00 += rw0[4*j4]*h0.x + rw0[4*j4+1]*h0.y + rw0[4*j4+2]*h0.z + rw0[4*j4+3]*h0.w;
            a01 += rw0[4*j4]*h1.x + rw0[4*j4+1]*h1.y + rw0[4*j4+2]*h1.z + rw0[4*j4+3]*h1.w;
            a10 += rw1[4*j4]*h0.x + rw1[4*j4+1]*h0.y + rw1[4*j4+2]*h0.z + rw1[4*j4+3]*h0.w;
            a11 += rw1[4*j4]*h1.x + rw1[4*j4+1]*h1.y + rw1[4*j4+2]*h1.z + rw1[4*j4+3]*h1.w;
        }
        float v00 = sigf(a00), v01 = sigf(a01), v10, v11;
        if (isTanh) { v10 = tanhfast(a10); v11 = tanhfast(a11); }
        else        { v10 = sigf(a10);     v11 = sigf(a11); }
        {
            int u0 = g0 & 127, ty0 = g0 >> 7;
            sG[(ty0 * 2 + 0) * H_ + u0] = v00;
            sG[(ty0 * 2 + 1) * H_ + u0] = v01;
            int u1 = g1 & 127, ty1 = g1 >> 7;
            sG[(ty1 * 2 + 0) * H_ + u1] = v10;
            sG[(ty1 * 2 + 1) * H_ + u1] = v11;
        }
        __syncthreads();
        {
            float iv = sG[(0 * 2 + b_upd) * H_ + u_upd];
            float fv = sG[(1 * 2 + b_upd) * H_ + u_upd];
            float gv = sG[(2 * 2 + b_upd) * H_ + u_upd];
            float ov = sG[(3 * 2 + b_upd) * H_ + u_upd];
            c = fv * c + iv * gv;
            float h = ov * tanhfast(c);
            h_last = h;
            sH[b_upd * H_ + u_upd] = h;
            g_hs[((size_t)t * B_ + row0 + b_upd) * H_ + u_upd] = h;
        }
        __syncthreads();
    }
    outp[HT_OFF + (size_t)(row0 + b_upd) * H_ + u_upd] = h_last;
    outp[CT_OFF + (size_t)(row0 + b_upd) * H_ + u_upd] = c;
}

// ---------------------------------------------------------------------------
// Kernel C (mma): fused MLP, 64-row tiles, hs pre-split hi/lo at staging.
// 8 warps: mg=w&1 (32-row groups), ng=w>>1 (16-col groups); nt 2 n8-tiles.
// NH in 8 chunks of 64; GEMM2 accumulates in regs across chunks.
// ---------------------------------------------------------------------------
#define SAh_  0
#define SAl_  (SAh_  + 64 * 132)     // 8448
#define SB1h_ (SAl_  + 64 * 132)     // 16896
#define SB1l_ (SB1h_ + 128 * 72)     // 26112
#define SHid_ (SB1l_ + 128 * 72)     // 35328
#define SW2h_ (SHid_ + 64 * 68)      // 39680
#define SW2l_ (SW2h_ + 64 * 72)      // 44288
#define SB1V_ (SW2l_ + 64 * 72)      // 48896
#define SB2V_ (SB1V_ + 512)          // 49408
#define MLP_SMEM_BYTES ((SB2V_ + 64) * 4)   // 197888

__global__ void __launch_bounds__(256, 1) mlp_mma_kernel(const float* __restrict__ b1,
                                                         const float* __restrict__ b2,
                                                         float* __restrict__ outp) {
    extern __shared__ float sm[];
    const int tid = threadIdx.x;
    const int lane = tid & 31;
    const int w = tid >> 5;
    const int mg = w & 1;          // 2 row groups of 32
    const int ng = w >> 1;         // 4 col groups of 16
    const size_t rowBase = (size_t)blockIdx.x * 64;

    const int rA = mg * 32 + (lane >> 2);
    const int kA = lane & 3;
    const int cB = lane >> 2;
    const int kB = lane & 3;

    // stage hs tile [64][128], split hi/lo at staging (stride 132 = 4 mod 32)
    for (int i = tid; i < 2048; i += 256) {
        int r = i >> 5, c4 = i & 31;
        float4 v = reinterpret_cast<const float4*>(g_hs)[(rowBase + r) * 32 + c4];
        uint32_t h, l;
        float* dh = &sm[SAh_ + r * 132 + c4 * 4];
        float* dl = &sm[SAl_ + r * 132 + c4 * 4];
        tf32_split(v.x, h, l); dh[0] = __uint_as_float(h); dl[0] = __uint_as_float(l);
        tf32_split(v.y, h, l); dh[1] = __uint_as_float(h); dl[1] = __uint_as_float(l);
        tf32_split(v.z, h, l); dh[2] = __uint_as_float(h); dl[2] = __uint_as_float(l);
        tf32_split(v.w, h, l); dh[3] = __uint_as_float(h); dl[3] = __uint_as_float(l);
    }
    for (int i = tid; i < NH_; i += 256) sm[SB1V_ + i] = b1[i];
    if (tid < O_) sm[SB2V_ + tid] = b2[tid];

    float accO[2][2][4];
#pragma unroll
    for (int mf = 0; mf < 2; mf++)
#pragma unroll
        for (int nt = 0; nt < 2; nt++)
#pragma unroll
            for (int q = 0; q < 4; q++) accO[mf][nt][q] = 0.f;

    for (int c = 0; c < 8; c++) {
        __syncthreads();   // protect sB1/sW2/sHid (and sA staging on c=0)
        for (int i = tid; i < 2048; i += 256) {     // W1 chunk [128k][64n] hi/lo
            int k = i >> 4, n4 = i & 15;
            *reinterpret_cast<float4*>(&sm[SB1h_ + k * 72 + n4 * 4]) =
                reinterpret_cast<const float4*>(g_W1h)[k * 128 + c * 16 + n4];
            *reinterpret_cast<float4*>(&sm[SB1l_ + k * 72 + n4 * 4]) =
                reinterpret_cast<const float4*>(g_W1l)[k * 128 + c * 16 + n4];
        }
        for (int i = tid; i < 1024; i += 256) {     // W2 chunk [64k][64o] hi/lo
            int k = i >> 4, n4 = i & 15;
            *reinterpret_cast<float4*>(&sm[SW2h_ + k * 72 + n4 * 4]) =
                reinterpret_cast<const float4*>(g_W2h)[(c * 64 + k) * 16 + n4];
            *reinterpret_cast<float4*>(&sm[SW2l_ + k * 72 + n4 * 4]) =
                reinterpret_cast<const float4*>(g_W2l)[(c * 64 + k) * 16 + n4];
        }
        __syncthreads();

        // ---- GEMM1: hidden = hs @ W1_chunk^T  (M=64, N=64, K=128) ----
        float acc[2][2][4];
#pragma unroll
        for (int mf = 0; mf < 2; mf++)
#pragma unroll
            for (int nt = 0; nt < 2; nt++)
#pragma unroll
                for (int q = 0; q < 4; q++) acc[mf][nt][q] = 0.f;

#pragma unroll 4
        for (int ks = 0; ks < 16; ks++) {
            uint32_t Ah[2][4], Al[2][4];
#pragma unroll
            for (int mf = 0; mf < 2; mf++) {
                int r = rA + mf * 16;
                int k = ks * 8 + kA;
                Ah[mf][0] = __float_as_uint(sm[SAh_ + r * 132 + k]);
                Ah[mf][1] = __float_as_uint(sm[SAh_ + (r + 8) * 132 + k]);
                Ah[mf][2] = __float_as_uint(sm[SAh_ + r * 132 + k + 4]);
                Ah[mf][3] = __float_as_uint(sm[SAh_ + (r + 8) * 132 + k + 4]);
                Al[mf][0] = __float_as_uint(sm[SAl_ + r * 132 + k]);
                Al[mf][1] = __float_as_uint(sm[SAl_ + (r + 8) * 132 + k]);
                Al[mf][2] = __float_as_uint(sm[SAl_ + r * 132 + k + 4]);
                Al[mf][3] = __float_as_uint(sm[SAl_ + (r + 8) * 132 + k + 4]);
            }
#pragma unroll
            for (int nt = 0; nt < 2; nt++) {
                int n = ng * 16 + nt * 8 + cB;
                int k = ks * 8 + kB;
                uint32_t Bh[2], Bl[2];
                Bh[0] = __float_as_uint(sm[SB1h_ + k * 72 + n]);
                Bh[1] = __float_as_uint(sm[SB1h_ + (k + 4) * 72 + n]);
                Bl[0] = __float_as_uint(sm[SB1l_ + k * 72 + n]);
                Bl[1] = __float_as_uint(sm[SB1l_ + (k + 4) * 72 + n]);
#pragma unroll
                for (int mf = 0; mf < 2; mf++) {
                    mma8(acc[mf][nt], Ah[mf], Bh);
                    mma8(acc[mf][nt], Al[mf], Bh);
                    mma8(acc[mf][nt], Ah[mf], Bl);
                }
            }
        }

        // epilogue: +b1, relu -> sHid fp32 (stride 68)
#pragma unroll
        for (int mf = 0; mf < 2; mf++)
#pragma unroll
            for (int nt = 0; nt < 2; nt++) {
                int r = rA + mf * 16;
                int col = ng * 16 + nt * 8 + (lane & 3) * 2;
                float bb0 = sm[SB1V_ + c * 64 + col];
                float bb1 = sm[SB1V_ + c * 64 + col + 1];
                float2 v0, v1;
                v0.x = fmaxf(acc[mf][nt][0] + bb0, 0.f);
                v0.y = fmaxf(acc[mf][nt][1] + bb1, 0.f);
                v1.x = fmaxf(acc[mf][nt][2] + bb0, 0.f);
                v1.y = fmaxf(acc[mf][nt][3] + bb1, 0.f);
                *reinterpret_cast<float2*>(&sm[SHid_ + r * 68 + col]) = v0;
                *reinterpret_cast<float2*>(&sm[SHid_ + (r + 8) * 68 + col]) = v1;
            }
        __syncthreads();

        // ---- GEMM2: accO += hidden @ W2_chunk^T  (M=64, N=64, K=64) ----
#pragma unroll 2
        for (int ks = 0; ks < 8; ks++) {
            uint32_t Ah[2][4], Al[2][4];
#pragma unroll
            for (int mf = 0; mf < 2; mf++) {
                int r = rA + mf * 16;
                int k = ks * 8 + kA;
                float a0 = sm[SHid_ + r * 68 + k];
                float a1 = sm[SHid_ + (r + 8) * 68 + k];
                float a2 = sm[SHid_ + r * 68 + k + 4];
                float a3 = sm[SHid_ + (r + 8) * 68 + k + 4];
                tf32_split(a0, Ah[mf][0], Al[mf][0]);
                tf32_split(a1, Ah[mf][1], Al[mf][1]);
                tf32_split(a2, Ah[mf][2], Al[mf][2]);
                tf32_split(a3, Ah[mf][3], Al[mf][3]);
            }
#pragma unroll
            for (int nt = 0; nt < 2; nt++) {
                int n = ng * 16 + nt * 8 + cB;
                int k = ks * 8 + kB;
                uint32_t Bh[2], Bl[2];
                Bh[0] = __float_as_uint(sm[SW2h_ + k * 72 + n]);
                Bh[1] = __float_as_uint(sm[SW2h_ + (k + 4) * 72 + n]);
                Bl[0] = __float_as_uint(sm[SW2l_ + k * 72 + n]);
                Bl[1] = __float_as_uint(sm[SW2l_ + (k + 4) * 72 + n]);
#pragma unroll
                for (int mf = 0; mf < 2; mf++) {
                    mma8(accO[mf][nt], Ah[mf], Bh);
                    mma8(accO[mf][nt], Al[mf], Bh);
                    mma8(accO[mf][nt], Ah[mf], Bl);
                }
            }
        }
    }

    // output: +b2, store
#pragma unroll
    for (int mf = 0; mf < 2; mf++) {
        size_t r0 = rowBase + rA + mf * 16;
#pragma unroll
        for (int nt = 0; nt < 2; nt++) {
            int col = ng * 16 + nt * 8 + (lane & 3) * 2;
            float bo0 = sm[SB2V_ + col];
            float bo1 = sm[SB2V_ + col + 1];
            float2 v0, v1;
            v0.x = accO[mf][nt][0] + bo0;
            v0.y = accO[mf][nt][1] + bo1;
            v1.x = accO[mf][nt][2] + bo0;
            v1.y = accO[mf][nt][3] + bo1;
            *reinterpret_cast<float2*>(outp + r0 * O_ + col) = v0;
            *reinterpret_cast<float2*>(outp + (r0 + 8) * O_ + col) = v1;
        }
    }
}

// ---------------------------------------------------------------------------
// Launcher
// ---------------------------------------------------------------------------
extern "C" void kernel_launch(void* const* d_in, const int* in_sizes, int n_in,
                              void* d_out, int out_size) {
    const float* x    = (const float*)d_in[0];
    const float* Wih  = (const float*)d_in[1];
    const float* Whh  = (const float*)d_in[2];
    const float* bih  = (const float*)d_in[3];
    const float* bhh  = (const float*)d_in[4];
    const float* W1   = (const float*)d_in[5];
    const float* b1   = (const float*)d_in[6];
    const float* W2   = (const float*)d_in[7];
    const float* b2   = (const float*)d_in[8];
    float* out = (float*)d_out;

    cudaFuncSetAttribute(xg_mma_kernel,  cudaFuncAttributeMaxDynamicSharedMemorySize, XG_SMEM_BYTES);
    cudaFuncSetAttribute(lstm_kernel,    cudaFuncAttributeMaxDynamicSharedMemorySize, LSTM_SMEM_BYTES);
    cudaFuncSetAttribute(mlp_mma_kernel, cudaFuncAttributeMaxDynamicSharedMemorySize, MLP_SMEM_BYTES);

    prep_kernel<<<64, 256>>>(Wih, W1, W2);
    xg_mma_kernel<<<(T_ * B_) / 128, 256, XG_SMEM_BYTES>>>(x, bih, bhh);
    lstm_kernel<<<B_ / 2, 256, LSTM_SMEM_BYTES>>>(Whh, out);
    mlp_mma_kernel<<<(T_ * B_) / 64, 256, MLP_SMEM_BYTES>>>(b1, b2, out);
}

// round 10
// speedup vs baseline: 1.5618x; 1.5618x over previous
#include <cuda_runtime.h>
#include <cstdint>

// ---------------------------------------------------------------------------
// Problem constants
// ---------------------------------------------------------------------------
#define T_  2048
#define B_  256
#define I_  64
#define H_  128
#define G4_ 512   // 4*H
#define NH_ 512
#define O_  64

// Device-global scratch (allocation-free rule)
__device__ float g_xg[(size_t)T_ * B_ * G4_];   // [T,B,4H]
__device__ float g_hs[(size_t)T_ * B_ * H_];    // [T,B,H]
__device__ float g_Wxh[I_ * G4_];               // [k=64][g=512] tf32 hi (transposed W_ih)
__device__ float g_Wxl[I_ * G4_];
__device__ float g_W1h[H_ * NH_];               // [k=128][nh=512] tf32 hi (transposed W1)
__device__ float g_W1l[H_ * NH_];
__device__ float g_W2h[NH_ * O_];               // [nh=512][o=64]  tf32 hi (transposed W2)
__device__ float g_W2l[NH_ * O_];

// Output layout: out[T,B,O] | hT[1,B,H] | cT[1,B,H]
#define OUT_ELEMS ((size_t)T_ * B_ * O_)
#define HT_OFF    (OUT_ELEMS)
#define CT_OFF    (OUT_ELEMS + (size_t)B_ * H_)

__device__ __forceinline__ float sigf(float x)      { return 1.f / (1.f + __expf(-x)); }
__device__ __forceinline__ float tanhfast(float x)  { return 2.f / (1.f + __expf(-2.f * x)) - 1.f; }

// ---------------------------------------------------------------------------
// tf32 helpers (mma.sync works on base sm_103; tcgen05 does not — harness
// emits compute_103 PTX without the 'a' suffix)
// ---------------------------------------------------------------------------
__device__ __forceinline__ void tf32_split(float a, uint32_t& hi, uint32_t& lo) {
    uint32_t h;
    asm("cvt.rna.tf32.f32 %0, %1;" : "=r"(h) : "f"(a));
    float r = a - __uint_as_float(h);
    uint32_t l;
    asm("cvt.rna.tf32.f32 %0, %1;" : "=r"(l) : "f"(r));
    hi = h; lo = l;
}

__device__ __forceinline__ void mma8(float* d, const uint32_t* a, const uint32_t* b) {
    asm volatile("mma.sync.aligned.m16n8k8.row.col.f32.tf32.tf32.f32 "
                 "{%0,%1,%2,%3}, {%4,%5,%6,%7}, {%8,%9}, {%0,%1,%2,%3};"
                 : "+f"(d[0]), "+f"(d[1]), "+f"(d[2]), "+f"(d[3])
                 : "r"(a[0]), "r"(a[1]), "r"(a[2]), "r"(a[3]), "r"(b[0]), "r"(b[1]));
}

// ---------------------------------------------------------------------------
// Kernel P: pre-split weights into tf32 hi/lo planes (transposed for col-major B)
// ---------------------------------------------------------------------------
__global__ void prep_kernel(const float* __restrict__ Wih,
                            const float* __restrict__ W1,
                            const float* __restrict__ W2) {
    int i0 = blockIdx.x * blockDim.x + threadIdx.x;
    int st = gridDim.x * blockDim.x;
    for (int i = i0; i < G4_ * I_; i += st) {        // W_ih [g][k] -> [k][g]
        int g = i >> 6, k = i & 63;
        uint32_t h, l;
        tf32_split(Wih[i], h, l);
        g_Wxh[k * G4_ + g] = __uint_as_float(h);
        g_Wxl[k * G4_ + g] = __uint_as_float(l);
    }
    for (int i = i0; i < NH_ * H_; i += st) {        // W1 [nh][k] -> [k][nh]
        int nh = i >> 7, k = i & 127;
        uint32_t h, l;
        tf32_split(W1[i], h, l);
        g_W1h[k * NH_ + nh] = __uint_as_float(h);
        g_W1l[k * NH_ + nh] = __uint_as_float(l);
    }
    for (int i = i0; i < O_ * NH_; i += st) {        // W2 [o][nh] -> [nh][o]
        int o = i >> 9, nh = i & 511;
        uint32_t h, l;
        tf32_split(W2[i], h, l);
        g_W2h[nh * O_ + o] = __uint_as_float(h);
        g_W2l[nh * O_ + o] = __uint_as_float(l);
    }
}

// ---------------------------------------------------------------------------
// Kernel A (mma): xg[row,g] = x @ W_ih^T + bias.  128 rows/CTA, 8 gate-chunks
// of 64.  A (x) pre-split into hi/lo tf32 planes at staging; 3xTF32 mma.
// SMEM 108.5KB -> 2 CTAs/SM.  Strides: A 68 (=4 mod 32), B 72 (=8 mod 32).
// ---------------------------------------------------------------------------
#define XAh_ 0
#define XAl_ (XAh_ + 128 * 68)    // 8704
#define XBh_ (XAl_ + 128 * 68)    // 17408
#define XBl_ (XBh_ +  64 * 72)    // 22016
#define XBI_ (XBl_ +  64 * 72)    // 26624
#define XG_SMEM_BYTES ((XBI_ + 512) * 4)   // 108544

__global__ void __launch_bounds__(256, 2) xg_mma_kernel(const float* __restrict__ x,
                                                        const float* __restrict__ bih,
                                                        const float* __restrict__ bhh) {
    extern __shared__ float sm[];
    const int tid = threadIdx.x;
    const int lane = tid & 31;
    const int w = tid >> 5;
    const int mg = w & 3;          // 4 row groups of 32
    const int nh2 = w >> 2;        // 2 col halves of 32
    const size_t rowBase = (size_t)blockIdx.x * 128;

    const int rA = mg * 32 + (lane >> 2);
    const int kA = lane & 3;
    const int cB = lane >> 2;
    const int kB = lane & 3;

    // stage x tile [128][64], split hi/lo at staging
    for (int i = tid; i < 2048; i += 256) {
        int r = i >> 4, c4 = i & 15;
        float4 v = reinterpret_cast<const float4*>(x)[(rowBase + r) * 16 + c4];
        uint32_t h, l;
        float* dh = &sm[XAh_ + r * 68 + c4 * 4];
        float* dl = &sm[XAl_ + r * 68 + c4 * 4];
        tf32_split(v.x, h, l); dh[0] = __uint_as_float(h); dl[0] = __uint_as_float(l);
        tf32_split(v.y, h, l); dh[1] = __uint_as_float(h); dl[1] = __uint_as_float(l);
        tf32_split(v.z, h, l); dh[2] = __uint_as_float(h); dl[2] = __uint_as_float(l);
        tf32_split(v.w, h, l); dh[3] = __uint_as_float(h); dl[3] = __uint_as_float(l);
    }
    for (int i = tid; i < G4_; i += 256) sm[XBI_ + i] = bih[i] + bhh[i];

    for (int ch = 0; ch < 8; ch++) {
        __syncthreads();   // protect B buffers (and A staging on ch=0)
        for (int i = tid; i < 1024; i += 256) {     // B chunk [64 k][64 g] hi/lo
            int k = i >> 4, n4 = i & 15;
            *reinterpret_cast<float4*>(&sm[XBh_ + k * 72 + n4 * 4]) =
                reinterpret_cast<const float4*>(g_Wxh)[k * 128 + ch * 16 + n4];
            *reinterpret_cast<float4*>(&sm[XBl_ + k * 72 + n4 * 4]) =
                reinterpret_cast<const float4*>(g_Wxl)[k * 128 + ch * 16 + n4];
        }
        __syncthreads();

        float acc[2][4][4];
#pragma unroll
        for (int mf = 0; mf < 2; mf++)
#pragma unroll
            for (int nt = 0; nt < 4; nt++)
#pragma unroll
                for (int q = 0; q < 4; q++) acc[mf][nt][q] = 0.f;

#pragma unroll
        for (int ks = 0; ks < 8; ks++) {
            uint32_t Ah[2][4], Al[2][4];
#pragma unroll
            for (int mf = 0; mf < 2; mf++) {
                int r = rA + mf * 16;
                int k = ks * 8 + kA;
                Ah[mf][0] = __float_as_uint(sm[XAh_ + r * 68 + k]);
                Ah[mf][1] = __float_as_uint(sm[XAh_ + (r + 8) * 68 + k]);
                Ah[mf][2] = __float_as_uint(sm[XAh_ + r * 68 + k + 4]);
                Ah[mf][3] = __float_as_uint(sm[XAh_ + (r + 8) * 68 + k + 4]);
                Al[mf][0] = __float_as_uint(sm[XAl_ + r * 68 + k]);
                Al[mf][1] = __float_as_uint(sm[XAl_ + (r + 8) * 68 + k]);
                Al[mf][2] = __float_as_uint(sm[XAl_ + r * 68 + k + 4]);
                Al[mf][3] = __float_as_uint(sm[XAl_ + (r + 8) * 68 + k + 4]);
            }
#pragma unroll
            for (int nt = 0; nt < 4; nt++) {
                int n = nh2 * 32 + nt * 8 + cB;
                int k = ks * 8 + kB;
                uint32_t Bh[2], Bl[2];
                Bh[0] = __float_as_uint(sm[XBh_ + k * 72 + n]);
                Bh[1] = __float_as_uint(sm[XBh_ + (k + 4) * 72 + n]);
                Bl[0] = __float_as_uint(sm[XBl_ + k * 72 + n]);
                Bl[1] = __float_as_uint(sm[XBl_ + (k + 4) * 72 + n]);
#pragma unroll
                for (int mf = 0; mf < 2; mf++) {
                    mma8(acc[mf][nt], Ah[mf], Bh);
                    mma8(acc[mf][nt], Al[mf], Bh);
                    mma8(acc[mf][nt], Ah[mf], Bl);
                }
            }
        }

        // write chunk to g_xg (+bias)
#pragma unroll
        for (int mf = 0; mf < 2; mf++) {
            size_t r0 = rowBase + rA + mf * 16;
#pragma unroll
            for (int nt = 0; nt < 4; nt++) {
                int col = ch * 64 + nh2 * 32 + nt * 8 + (lane & 3) * 2;
                float bb0 = sm[XBI_ + col];
                float bb1 = sm[XBI_ + col + 1];
                float2 v0, v1;
                v0.x = acc[mf][nt][0] + bb0;
                v0.y = acc[mf][nt][1] + bb1;
                v1.x = acc[mf][nt][2] + bb0;
                v1.y = acc[mf][nt][3] + bb1;
                *reinterpret_cast<float2*>(&g_xg[r0 * G4_ + col]) = v0;
                *reinterpret_cast<float2*>(&g_xg[(r0 + 8) * G4_ + col]) = v1;
            }
        }
    }
}

// ---------------------------------------------------------------------------
// Kernel B: persistent LSTM scan.  KS=100 k in SMEM (204.8KB), KR=28 k in regs.
// Stride = 25 float4 per gate row (25 ODD => bank stride 100 mod 32 = 4, and
// within an 8-lane LDS.128 phase banks 4*l are all distinct: conflict-free —
// the invariant KS=80 broke in R9).
// ---------------------------------------------------------------------------
#define KS_ 100
#define KR_ 28
#define LSTM_SMEM_BYTES ((G4_ * KS_ + 2 * H_ + 8 * H_) * 4)   // 209920

__global__ void __launch_bounds__(256, 1) lstm_kernel(const float* __restrict__ Whh,
                                                      float* __restrict__ outp) {
    extern __shared__ float smem[];
    float* sW = smem;                 // [512][100]
    float* sH = sW + G4_ * KS_;       // [2][128]
    float* sG = sH + 2 * H_;          // [4 types][2 rows][128 units]

    const int tid = threadIdx.x;
    const int row0 = blockIdx.x * 2;
    const int g0 = tid, g1 = tid + 256;

    const float4* W4 = reinterpret_cast<const float4*>(Whh);
    float4* sW4 = reinterpret_cast<float4*>(sW);
    for (int idx = tid; idx < G4_ * 25; idx += 256) {
        int g = idx / 25, k4 = idx % 25;
        sW4[g * 25 + k4] = W4[g * 32 + k4];
    }
    float rw0[KR_], rw1[KR_];
#pragma unroll
    for (int j = 0; j < KR_; j++) {
        rw0[j] = Whh[g0 * H_ + KS_ + j];
        rw1[j] = Whh[g1 * H_ + KS_ + j];
    }
    sH[tid] = 0.f;
    float c = 0.f;
    float h_last = 0.f;
    __syncthreads();

    const float4* w0p = sW4 + g0 * 25;
    const float4* w1p = sW4 + g1 * 25;
    const float4* h0p = reinterpret_cast<const float4*>(sH);
    const float4* h1p = reinterpret_cast<const float4*>(sH + H_);

    size_t pb0 = (size_t)row0 * G4_;
    float xn00 = g_xg[pb0 + g0], xn01 = g_xg[pb0 + G4_ + g0];
    float xn10 = g_xg[pb0 + g1], xn11 = g_xg[pb0 + G4_ + g1];

    const int b_upd = tid >> 7, u_upd = tid & 127;
    const bool isTanh = (g1 < 384);

    for (int t = 0; t < T_; t++) {
        float a00 = xn00, a01 = xn01, a10 = xn10, a11 = xn11;
        if (t + 1 < T_) {
            size_t nb = ((size_t)(t + 1) * B_ + row0) * G4_;
            xn00 = g_xg[nb + g0]; xn01 = g_xg[nb + G4_ + g0];
            xn10 = g_xg[nb + g1]; xn11 = g_xg[nb + G4_ + g1];
        }
#pragma unroll 5
        for (int k4 = 0; k4 < 25; k4++) {
            float4 w0 = w0p[k4], w1 = w1p[k4];
            float4 h0 = h0p[k4], h1 = h1p[k4];
            a00 += w0.x * h0.x + w0.y * h0.y + w0.z * h0.z + w0.w * h0.w;
            a01 += w0.x * h1.x + w0.y * h1.y + w0.z * h1.z + w0.w * h1.w;
            a10 += w1.x * h0.x + w1.y * h0.y + w1.z * h0.z + w1.w * h0.w;
            a11 += w1.x * h1.x + w1.y * h1.y + w1.z * h1.z + w1.w * h1.w;
        }
#pragma unroll
        for (int j4 = 0; j4 < 7; j4++) {   // register tail k = 100..127
            float4 h0 = h0p[25 + j4], h1 = h1p[25 + j4];
            a00 += rw0[4*j4]*h0.x + rw0[4*j4+1]*h0.y + rw0[4*j4+2]*h0.z + rw0[4*j4+3]*h0.w;
            a01 += rw0[4*j4]*h1.x + rw0[4*j4+1]*h1.y + rw0[4*j4+2]*h1.z + rw0[4*j4+3]*h1.w;
            a10 += rw1[4*j4]*h0.x + rw1[4*j4+1]*h0.y + rw1[4*j4+2]*h0.z + rw1[4*j4+3]*h0.w;
            a11 += rw1[4*j4]*h1.x + rw1[4*j4+1]*h1.y + rw1[4*j4+2]*h1.z + rw1[4*j4+3]*h1.w;
        }
        float v00 = sigf(a00), v01 = sigf(a01), v10, v11;
        if (isTanh) { v10 = tanhfast(a10); v11 = tanhfast(a11); }
        else        { v10 = sigf(a10);     v11 = sigf(a11); }
        {
            int u0 = g0 & 127, ty0 = g0 >> 7;
            sG[(ty0 * 2 + 0) * H_ + u0] = v00;
            sG[(ty0 * 2 + 1) * H_ + u0] = v01;
            int u1 = g1 & 127, ty1 = g1 >> 7;
            sG[(ty1 * 2 + 0) * H_ + u1] = v10;
            sG[(ty1 * 2 + 1) * H_ + u1] = v11;
        }
        __syncthreads();
        {
            float iv = sG[(0 * 2 + b_upd) * H_ + u_upd];
            float fv = sG[(1 * 2 + b_upd) * H_ + u_upd];
            float gv = sG[(2 * 2 + b_upd) * H_ + u_upd];
            float ov = sG[(3 * 2 + b_upd) * H_ + u_upd];
            c = fv * c + iv * gv;
            float h = ov * tanhfast(c);
            h_last = h;
            sH[b_upd * H_ + u_upd] = h;
            g_hs[((size_t)t * B_ + row0 + b_upd) * H_ + u_upd] = h;
        }
        __syncthreads();
    }
    outp[HT_OFF + (size_t)(row0 + b_upd) * H_ + u_upd] = h_last;
    outp[CT_OFF + (size_t)(row0 + b_upd) * H_ + u_upd] = c;
}

// ---------------------------------------------------------------------------
// Kernel C (mma): fused MLP — R8 version (128-row tiles, proven 2.04 ms).
// 8 warps: mg=w&3 (32-row groups), nh2=w>>2 (32-col halves), 4 n8-tiles.
// NH in 8 chunks of 64; GEMM2 accumulates in regs across chunks.
// ---------------------------------------------------------------------------
#define SA_    0                         // float offsets into dynamic smem
#define SB1H_  (SA_   + 128 * 132)       // 16896
#define SB1L_  (SB1H_ + 128 * 72)        // 26112
#define SHID_  (SB1L_ + 128 * 72)        // 35328
#define SW2H_  (SHID_ + 128 * 68)        // 44032
#define SW2L_  (SW2H_ +  64 * 72)        // 48640
#define SB1V_  (SW2L_ +  64 * 72)        // 53248
#define SB2V_  (SB1V_ + 512)             // 53760
#define MLP_SMEM_BYTES  ((SB2V_ + 64) * 4)   // 215296

__global__ void __launch_bounds__(256, 1) mlp_mma_kernel(const float* __restrict__ b1,
                                                         const float* __restrict__ b2,
                                                         float* __restrict__ outp) {
    extern __shared__ float sm[];
    const int tid = threadIdx.x;
    const int lane = tid & 31;
    const int w = tid >> 5;
    const int mg = w & 3;          // row group (32 rows)
    const int nh2 = w >> 2;        // col half (32 cols of 64-chunk)
    const size_t rowBase = (size_t)blockIdx.x * 128;

    const int rA = mg * 32 + (lane >> 2);
    const int kA = lane & 3;
    const int cB = lane >> 2;
    const int kB = lane & 3;

    // stage hs tile [128][128] -> sA stride 132
    for (int i = tid; i < 4096; i += 256) {
        int r = i >> 5, c4 = i & 31;
        float4 v = reinterpret_cast<const float4*>(g_hs)[(rowBase + r) * 32 + c4];
        *reinterpret_cast<float4*>(&sm[SA_ + r * 132 + c4 * 4]) = v;
    }
    for (int i = tid; i < NH_; i += 256) sm[SB1V_ + i] = b1[i];
    if (tid < O_) sm[SB2V_ + tid] = b2[tid];

    float accO[2][4][4];
#pragma unroll
    for (int mf = 0; mf < 2; mf++)
#pragma unroll
        for (int nt = 0; nt < 4; nt++)
#pragma unroll
            for (int q = 0; q < 4; q++) accO[mf][nt][q] = 0.f;

    for (int c = 0; c < 8; c++) {
        __syncthreads();   // frees sB1/sW2/sHid from previous chunk (and covers sA staging)
        // stage W1 chunk [128k][64n] hi/lo
        for (int i = tid; i < 2048; i += 256) {
            int k = i >> 4, n4 = i & 15;
            *reinterpret_cast<float4*>(&sm[SB1H_ + k * 72 + n4 * 4]) =
                reinterpret_cast<const float4*>(g_W1h)[k * 128 + c * 16 + n4];
            *reinterpret_cast<float4*>(&sm[SB1L_ + k * 72 + n4 * 4]) =
                reinterpret_cast<const float4*>(g_W1l)[k * 128 + c * 16 + n4];
        }
        // stage W2 chunk [64k][64o] hi/lo
        for (int i = tid; i < 1024; i += 256) {
            int k = i >> 4, n4 = i & 15;
            *reinterpret_cast<float4*>(&sm[SW2H_ + k * 72 + n4 * 4]) =
                reinterpret_cast<const float4*>(g_W2h)[(c * 64 + k) * 16 + n4];
            *reinterpret_cast<float4*>(&sm[SW2L_ + k * 72 + n4 * 4]) =
                reinterpret_cast<const float4*>(g_W2l)[(c * 64 + k) * 16 + n4];
        }
        __syncthreads();

        // ---- GEMM1: hidden_chunk = hs @ W1_chunk^T  (M=128, N=64, K=128) ----
        float acc[2][4][4];
#pragma unroll
        for (int mf = 0; mf < 2; mf++)
#pragma unroll
            for (int nt = 0; nt < 4; nt++)
#pragma unroll
                for (int q = 0; q < 4; q++) acc[mf][nt][q] = 0.f;

#pragma unroll 2
        for (int ks = 0; ks < 16; ks++) {
            uint32_t Ah[2][4], Al[2][4];
#pragma unroll
            for (int mf = 0; mf < 2; mf++) {
                int r = rA + mf * 16;
                int k = ks * 8 + kA;
                float a0 = sm[SA_ + r * 132 + k];
                float a1 = sm[SA_ + (r + 8) * 132 + k];
                float a2 = sm[SA_ + r * 132 + k + 4];
                float a3 = sm[SA_ + (r + 8) * 132 + k + 4];
                tf32_split(a0, Ah[mf][0], Al[mf][0]);
                tf32_split(a1, Ah[mf][1], Al[mf][1]);
                tf32_split(a2, Ah[mf][2], Al[mf][2]);
                tf32_split(a3, Ah[mf][3], Al[mf][3]);
            }
#pragma unroll
            for (int nt = 0; nt < 4; nt++) {
                int n = nh2 * 32 + nt * 8 + cB;
                int k = ks * 8 + kB;
                uint32_t Bh[2], Bl[2];
                Bh[0] = __float_as_uint(sm[SB1H_ + k * 72 + n]);
                Bh[1] = __float_as_uint(sm[SB1H_ + (k + 4) * 72 + n]);
                Bl[0] = __float_as_uint(sm[SB1L_ + k * 72 + n]);
                Bl[1] = __float_as_uint(sm[SB1L_ + (k + 4) * 72 + n]);
#pragma unroll
                for (int mf = 0; mf < 2; mf++) {
                    mma8(acc[mf][nt], Ah[mf], Bh);
                    mma8(acc[mf][nt], Ah[mf], Bl);
                    mma8(acc[mf][nt], Al[mf], Bh);
                }
            }
        }

        // epilogue: +b1, relu -> sHid (each warp writes only its own 32x32 block)
#pragma unroll
        for (int mf = 0; mf < 2; mf++)
#pragma unroll
            for (int nt = 0; nt < 4; nt++) {
                int r = rA + mf * 16;
                int col = nh2 * 32 + nt * 8 + (lane & 3) * 2;
                float bb0 = sm[SB1V_ + c * 64 + col];
                float bb1 = sm[SB1V_ + c * 64 + col + 1];
                float2 v0, v1;
                v0.x = fmaxf(acc[mf][nt][0] + bb0, 0.f);
                v0.y = fmaxf(acc[mf][nt][1] + bb1, 0.f);
                v1.x = fmaxf(acc[mf][nt][2] + bb0, 0.f);
                v1.y = fmaxf(acc[mf][nt][3] + bb1, 0.f);
                *reinterpret_cast<float2*>(&sm[SHID_ + r * 68 + col]) = v0;
                *reinterpret_cast<float2*>(&sm[SHID_ + (r + 8) * 68 + col]) = v1;
            }
        __syncthreads();

        // ---- GEMM2: accO += hidden_chunk @ W2_chunk^T  (M=128, N=64, K=64) ----
#pragma unroll 2
        for (int ks = 0; ks < 8; ks++) {
            uint32_t Ah[2][4], Al[2][4];
#pragma unroll
            for (int mf = 0; mf < 2; mf++) {
                int r = rA + mf * 16;
                int k = ks * 8 + kA;
                float a0 = sm[SHID_ + r * 68 + k];
                float a1 = sm[SHID_ + (r + 8) * 68 + k];
                float a2 = sm[SHID_ + r * 68 + k + 4];
                float a3 = sm[SHID_ + (r + 8) * 68 + k + 4];
                tf32_split(a0, Ah[mf][0], Al[mf][0]);
                tf32_split(a1, Ah[mf][1], Al[mf][1]);
                tf32_split(a2, Ah[mf][2], Al[mf][2]);
                tf32_split(a3, Ah[mf][3], Al[mf][3]);
            }
#pragma unroll
            for (int nt = 0; nt < 4; nt++) {
                int n = nh2 * 32 + nt * 8 + cB;
                int k = ks * 8 + kB;
                uint32_t Bh[2], Bl[2];
                Bh[0] = __float_as_uint(sm[SW2H_ + k * 72 + n]);
                Bh[1] = __float_as_uint(sm[SW2H_ + (k + 4) * 72 + n]);
                Bl[0] = __float_as_uint(sm[SW2L_ + k * 72 + n]);
                Bl[1] = __float_as_uint(sm[SW2L_ + (k + 4) * 72 + n]);
#pragma unroll
                for (int mf = 0; mf < 2; mf++) {
                    mma8(accO[mf][nt], Ah[mf], Bh);
                    mma8(accO[mf][nt], Ah[mf], Bl);
                    mma8(accO[mf][nt], Al[mf], Bh);
                }
            }
        }
    }

    // output: +b2, store (8-byte stores; col even)
#pragma unroll
    for (int mf = 0; mf < 2; mf++) {
        size_t r0 = rowBase + rA + mf * 16;
#pragma unroll
        for (int nt = 0; nt < 4; nt++) {
            int col = nh2 * 32 + nt * 8 + (lane & 3) * 2;
            float bo0 = sm[SB2V_ + col];
            float bo1 = sm[SB2V_ + col + 1];
            float2 v0, v1;
            v0.x = accO[mf][nt][0] + bo0;
            v0.y = accO[mf][nt][1] + bo1;
            v1.x = accO[mf][nt][2] + bo0;
            v1.y = accO[mf][nt][3] + bo1;
            *reinterpret_cast<float2*>(outp + r0 * O_ + col) = v0;
            *reinterpret_cast<float2*>(outp + (r0 + 8) * O_ + col) = v1;
        }
    }
}

// ---------------------------------------------------------------------------
// Launcher
// ---------------------------------------------------------------------------
extern "C" void kernel_launch(void* const* d_in, const int* in_sizes, int n_in,
                              void* d_out, int out_size) {
    const float* x    = (const float*)d_in[0];
    const float* Wih  = (const float*)d_in[1];
    const float* Whh  = (const float*)d_in[2];
    const float* bih  = (const float*)d_in[3];
    const float* bhh  = (const float*)d_in[4];
    const float* W1   = (const float*)d_in[5];
    const float* b1   = (const float*)d_in[6];
    const float* W2   = (const float*)d_in[7];
    const float* b2   = (const float*)d_in[8];
    float* out = (float*)d_out;

    cudaFuncSetAttribute(xg_mma_kernel,  cudaFuncAttributeMaxDynamicSharedMemorySize, XG_SMEM_BYTES);
    cudaFuncSetAttribute(lstm_kernel,    cudaFuncAttributeMaxDynamicSharedMemorySize, LSTM_SMEM_BYTES);
    cudaFuncSetAttribute(mlp_mma_kernel, cudaFuncAttributeMaxDynamicSharedMemorySize, MLP_SMEM_BYTES);

    prep_kernel<<<64, 256>>>(Wih, W1, W2);
    xg_mma_kernel<<<(T_ * B_) / 128, 256, XG_SMEM_BYTES>>>(x, bih, bhh);
    lstm_kernel<<<B_ / 2, 256, LSTM_SMEM_BYTES>>>(Whh, out);
    mlp_mma_kernel<<<(T_ * B_) / 128, 256, MLP_SMEM_BYTES>>>(b1, b2, out);
}